// round 15
// baseline (speedup 1.0000x reference)
#include <cuda_runtime.h>
#include <cuda_fp16.h>
#include <cstdint>

// ---------------------------------------------------------------------------
// GCN layer: out = relu( (A x) @ W + b )  ==  relu( A (x@W) + b )
// R14 structure; single change: gather inner loop software-pipelined (load
// group i+1 while FMAing group i) to hide L2 latency.
// ---------------------------------------------------------------------------

#define C_DIM 128
static constexpr int  N_NODES = 50000;
static constexpr int  B_MAX   = 4;
static constexpr int  E_MAX   = 800000;
static constexpr long Y_ELEMS = (long)B_MAX * N_NODES * C_DIM;

static constexpr int SCAN_CHUNK  = 1024;
static constexpr int SCAN_BLOCKS = (N_NODES + SCAN_CHUNK - 1) / SCAN_CHUNK; // 49

__device__ __align__(16) __half             g_yh[Y_ELEMS];     // 51.2 MB
__device__ __align__(16) int                g_deg[N_NODES + 4];
__device__ __align__(16) int                g_off[N_NODES + 4];
__device__ __align__(16) int                g_cur[N_NODES + 4];
__device__ int                              g_bsum[SCAN_BLOCKS];
__device__ int                              g_bbase[SCAN_BLOCKS];
__device__ __align__(16) unsigned long long g_ebuf[E_MAX];     // {val:hi, col:lo}

// ---------------------------------------------------------------------------
// CSR build
// ---------------------------------------------------------------------------
__global__ void zero_deg_kernel(int n) {
    int i = blockIdx.x * blockDim.x + threadIdx.x;
    if (i < n) g_deg[i] = 0;
}

__global__ void hist_kernel(const int* __restrict__ er, int E) {
    int e = blockIdx.x * blockDim.x + threadIdx.x;
    if (e < E) atomicAdd(&g_deg[er[e]], 1);
}

__global__ void __launch_bounds__(256) blocksum_kernel(int N) {
    __shared__ int wsum[8];
    const int tid  = threadIdx.x;
    const int lane = tid & 31;
    const int wid  = tid >> 5;
    const int i0   = blockIdx.x * SCAN_CHUNK + tid * 4;

    int4 d = make_int4(0, 0, 0, 0);
    if (i0 + 3 < N) {
        d = *reinterpret_cast<const int4*>(g_deg + i0);
    } else {
        if (i0 < N)     d.x = g_deg[i0];
        if (i0 + 1 < N) d.y = g_deg[i0 + 1];
        if (i0 + 2 < N) d.z = g_deg[i0 + 2];
    }
    int s = d.x + d.y + d.z + d.w;
#pragma unroll
    for (int o = 16; o > 0; o >>= 1) s += __shfl_down_sync(0xffffffffu, s, o);
    if (lane == 0) wsum[wid] = s;
    __syncthreads();
    if (tid == 0) {
        int t = 0;
#pragma unroll
        for (int w = 0; w < 8; ++w) t += wsum[w];
        g_bsum[blockIdx.x] = t;
    }
}

__global__ void scan_bsums_kernel(int nb, int N) {
    const int lane = threadIdx.x;
    int carry = 0;
    for (int base = 0; base < nb; base += 32) {
        const int i = base + lane;
        const int v0 = (i < nb) ? g_bsum[i] : 0;
        int v = v0;
#pragma unroll
        for (int o = 1; o < 32; o <<= 1) {
            const int t = __shfl_up_sync(0xffffffffu, v, o);
            if (lane >= o) v += t;
        }
        if (i < nb) g_bbase[i] = carry + v - v0;
        carry += __shfl_sync(0xffffffffu, v, 31);
    }
    if (lane == 0) g_off[N] = carry;
}

__global__ void __launch_bounds__(256) scanout_kernel(int N) {
    __shared__ int wbase[8];
    const int tid  = threadIdx.x;
    const int lane = tid & 31;
    const int wid  = tid >> 5;
    const int i0   = blockIdx.x * SCAN_CHUNK + tid * 4;

    int4 d = make_int4(0, 0, 0, 0);
    if (i0 + 3 < N) {
        d = *reinterpret_cast<const int4*>(g_deg + i0);
    } else {
        if (i0 < N)     d.x = g_deg[i0];
        if (i0 + 1 < N) d.y = g_deg[i0 + 1];
        if (i0 + 2 < N) d.z = g_deg[i0 + 2];
    }
    const int t = d.x + d.y + d.z + d.w;

    int v = t;
#pragma unroll
    for (int o = 1; o < 32; o <<= 1) {
        const int u = __shfl_up_sync(0xffffffffu, v, o);
        if (lane >= o) v += u;
    }
    if (lane == 31) wbase[wid] = v;
    __syncthreads();
    if (tid == 0) {
        int run = 0;
#pragma unroll
        for (int w = 0; w < 8; ++w) { const int tmp = wbase[w]; wbase[w] = run; run += tmp; }
    }
    __syncthreads();

    const int base = g_bbase[blockIdx.x] + wbase[wid] + (v - t);
    int4 off;
    off.x = base;
    off.y = off.x + d.x;
    off.z = off.y + d.y;
    off.w = off.z + d.z;

    if (i0 + 3 < N) {
        *reinterpret_cast<int4*>(g_off + i0) = off;
        *reinterpret_cast<int4*>(g_cur + i0) = off;
    } else {
        if (i0 < N)     { g_off[i0]     = off.x; g_cur[i0]     = off.x; }
        if (i0 + 1 < N) { g_off[i0 + 1] = off.y; g_cur[i0 + 1] = off.y; }
        if (i0 + 2 < N) { g_off[i0 + 2] = off.z; g_cur[i0 + 2] = off.z; }
    }
}

__global__ void scatter_kernel(const int*   __restrict__ er,
                               const int*   __restrict__ ec,
                               const float* __restrict__ ev,
                               int E) {
    int e = blockIdx.x * blockDim.x + threadIdx.x;
    if (e >= E) return;
    const int pos = atomicAdd(&g_cur[er[e]], 1);
    const unsigned long long rec =
        ((unsigned long long)__float_as_uint(ev[e]) << 32) | (unsigned)ec[e];
    g_ebuf[pos] = rec;
}

// ---------------------------------------------------------------------------
// HMMA GEMM (unchanged)
// ---------------------------------------------------------------------------
static constexpr int SPITCH = 136;

__device__ __forceinline__ uint32_t smem_u32(const void* p) {
    return (uint32_t)__cvta_generic_to_shared(p);
}
__device__ __forceinline__ void ldsm_x4(uint32_t& r0, uint32_t& r1,
                                        uint32_t& r2, uint32_t& r3, uint32_t addr) {
    asm volatile("ldmatrix.sync.aligned.m8n8.x4.shared.b16 {%0,%1,%2,%3}, [%4];"
                 : "=r"(r0), "=r"(r1), "=r"(r2), "=r"(r3) : "r"(addr));
}
__device__ __forceinline__ void ldsm_x4_t(uint32_t& r0, uint32_t& r1,
                                          uint32_t& r2, uint32_t& r3, uint32_t addr) {
    asm volatile("ldmatrix.sync.aligned.m8n8.x4.trans.shared.b16 {%0,%1,%2,%3}, [%4];"
                 : "=r"(r0), "=r"(r1), "=r"(r2), "=r"(r3) : "r"(addr));
}
__device__ __forceinline__ void mma_16816(float& d0, float& d1, float& d2, float& d3,
                                          uint32_t a0, uint32_t a1, uint32_t a2, uint32_t a3,
                                          uint32_t b0, uint32_t b1) {
    asm volatile(
        "mma.sync.aligned.m16n8k16.row.col.f32.f16.f16.f32 "
        "{%0,%1,%2,%3}, {%4,%5,%6,%7}, {%8,%9}, {%0,%1,%2,%3};"
        : "+f"(d0), "+f"(d1), "+f"(d2), "+f"(d3)
        : "r"(a0), "r"(a1), "r"(a2), "r"(a3), "r"(b0), "r"(b1));
}

__global__ void __launch_bounds__(256)
gemm_kernel(const float* __restrict__ x,
            const float* __restrict__ W,
            int total_rows) {
    extern __shared__ __half sh[];
    __half* As = sh;
    __half* Ws = sh + 128 * SPITCH;

    const int tid    = threadIdx.x;
    const int lane   = tid & 31;
    const int warp   = tid >> 5;
    const int warp_m = warp >> 1;
    const int warp_n = warp & 1;
    const long row0  = (long)blockIdx.x * 128;

    {
        const float4* Wg = reinterpret_cast<const float4*>(W);
        const float4* Ag = reinterpret_cast<const float4*>(x);
#pragma unroll
        for (int j = 0; j < 16; ++j) {
            const int i  = tid + j * 256;
            const int r  = i >> 5;
            const int c4 = i & 31;
            {
                const float4 v = __ldg(Wg + i);
                __half2 h0 = __floats2half2_rn(v.x, v.y);
                __half2 h1 = __floats2half2_rn(v.z, v.w);
                uint2 pk;
                pk.x = *reinterpret_cast<const unsigned*>(&h0);
                pk.y = *reinterpret_cast<const unsigned*>(&h1);
                *reinterpret_cast<uint2*>(Ws + r * SPITCH + c4 * 4) = pk;
            }
            {
                const long gr = row0 + r;
                float4 v = make_float4(0.f, 0.f, 0.f, 0.f);
                if (gr < total_rows) v = __ldcs(Ag + gr * 32 + c4);
                __half2 h0 = __floats2half2_rn(v.x, v.y);
                __half2 h1 = __floats2half2_rn(v.z, v.w);
                uint2 pk;
                pk.x = *reinterpret_cast<const unsigned*>(&h0);
                pk.y = *reinterpret_cast<const unsigned*>(&h1);
                *reinterpret_cast<uint2*>(As + r * SPITCH + c4 * 4) = pk;
            }
        }
    }
    __syncthreads();

    const int lrow = lane & 15;
    const int lcol = (lane >> 4) * 8;
    const uint32_t a_base = smem_u32(As) +
        (uint32_t)(((warp_m * 32 + lrow) * SPITCH + lcol) * 2);
    const uint32_t b_base = smem_u32(Ws) +
        (uint32_t)((lrow * SPITCH + warp_n * 64 + lcol) * 2);

    float acc[2][8][4];
#pragma unroll
    for (int mt = 0; mt < 2; ++mt)
#pragma unroll
        for (int nt = 0; nt < 8; ++nt)
#pragma unroll
            for (int q = 0; q < 4; ++q) acc[mt][nt][q] = 0.f;

#pragma unroll
    for (int kk = 0; kk < 8; ++kk) {
        uint32_t a[2][4];
        ldsm_x4(a[0][0], a[0][1], a[0][2], a[0][3],
                a_base + (uint32_t)(kk * 16 * 2));
        ldsm_x4(a[1][0], a[1][1], a[1][2], a[1][3],
                a_base + (uint32_t)((16 * SPITCH + kk * 16) * 2));

        uint32_t b[4][4];
#pragma unroll
        for (int nt16 = 0; nt16 < 4; ++nt16) {
            ldsm_x4_t(b[nt16][0], b[nt16][1], b[nt16][2], b[nt16][3],
                      b_base + (uint32_t)((kk * 16 * SPITCH + nt16 * 16) * 2));
        }

#pragma unroll
        for (int mt = 0; mt < 2; ++mt)
#pragma unroll
            for (int nt16 = 0; nt16 < 4; ++nt16) {
                mma_16816(acc[mt][nt16 * 2][0], acc[mt][nt16 * 2][1],
                          acc[mt][nt16 * 2][2], acc[mt][nt16 * 2][3],
                          a[mt][0], a[mt][1], a[mt][2], a[mt][3],
                          b[nt16][0], b[nt16][1]);
                mma_16816(acc[mt][nt16 * 2 + 1][0], acc[mt][nt16 * 2 + 1][1],
                          acc[mt][nt16 * 2 + 1][2], acc[mt][nt16 * 2 + 1][3],
                          a[mt][0], a[mt][1], a[mt][2], a[mt][3],
                          b[nt16][2], b[nt16][3]);
            }
    }

    __syncthreads();
    {
        const int g = lane >> 2;
        const int c = (lane & 3) * 2;
#pragma unroll
        for (int mt = 0; mt < 2; ++mt) {
#pragma unroll
            for (int nt = 0; nt < 8; ++nt) {
                const int row = warp_m * 32 + mt * 16 + g;
                const int col = warp_n * 64 + nt * 8 + c;
                __half2 lo = __floats2half2_rn(acc[mt][nt][0], acc[mt][nt][1]);
                __half2 hi = __floats2half2_rn(acc[mt][nt][2], acc[mt][nt][3]);
                *reinterpret_cast<__half2*>(As + row * SPITCH + col)       = lo;
                *reinterpret_cast<__half2*>(As + (row + 8) * SPITCH + col) = hi;
            }
        }
    }
    __syncthreads();
    {
#pragma unroll
        for (int j = 0; j < 8; ++j) {
            const int chunk = tid + j * 256;
            const int r   = chunk >> 4;
            const int c16 = chunk & 15;
            const long gr = row0 + r;
            if (gr < total_rows) {
                const uint4 v = *reinterpret_cast<const uint4*>(As + r * SPITCH + c16 * 8);
                *reinterpret_cast<uint4*>(g_yh + gr * C_DIM + c16 * 8) = v;
            }
        }
    }
}

// ---------------------------------------------------------------------------
// Gather: software-pipelined inner loop (issue loads for group i+1, FMA
// group i). Rest identical to R8/R14.
// ---------------------------------------------------------------------------
__device__ __forceinline__ void acc_pair(float4& a, float v, uint2 q) {
    const float2 fa = __half22float2(*reinterpret_cast<const __half2*>(&q.x));
    const float2 fb = __half22float2(*reinterpret_cast<const __half2*>(&q.y));
    a.x = fmaf(v, fa.x, a.x); a.y = fmaf(v, fa.y, a.y);
    a.z = fmaf(v, fb.x, a.z); a.w = fmaf(v, fb.y, a.w);
}

__global__ void __launch_bounds__(256)
gather_kernel(const float* __restrict__ bias,
              float*       __restrict__ out,
              int N) {
    const int lane = threadIdx.x & 31;
    const int warp = threadIdx.x >> 5;
    const int b    = blockIdx.y;

    const uint2* yb    = reinterpret_cast<const uint2*>(g_yh) + (size_t)b * N * 32;
    const float4 bias4 = __ldg(reinterpret_cast<const float4*>(bias) + lane);

    const int n_base = blockIdx.x * 64;

#pragma unroll 1
    for (int i = 0; i < 8; ++i) {
        const int n = n_base + warp * 8 + i;
        if (n >= N) return;

        const int st = __ldg(&g_off[n]);
        const int en = __ldg(&g_off[n + 1]);

        float4 a0 = make_float4(0.f, 0.f, 0.f, 0.f);
        float4 a1 = make_float4(0.f, 0.f, 0.f, 0.f);

        for (int base = st; base < en; base += 32) {
            const int m = min(32, en - base);
            unsigned long long pk = 0;
            if (lane < m) pk = __ldcs(&g_ebuf[base + lane]);

            int j = 0;
            if (m >= 2) {
                // prime: group (0,1)
                unsigned long long p0 = __shfl_sync(0xffffffffu, pk, 0);
                unsigned long long p1 = __shfl_sync(0xffffffffu, pk, 1);
                float v0 = __uint_as_float((unsigned)(p0 >> 32));
                float v1 = __uint_as_float((unsigned)(p1 >> 32));
                uint2 q0 = __ldg(yb + (size_t)(unsigned)(p0 & 0xffffffffu) * 32 + lane);
                uint2 q1 = __ldg(yb + (size_t)(unsigned)(p1 & 0xffffffffu) * 32 + lane);

                // steady state: while a full next group exists
                for (; j + 3 < m; j += 2) {
                    const unsigned long long p2 = __shfl_sync(0xffffffffu, pk, j + 2);
                    const unsigned long long p3 = __shfl_sync(0xffffffffu, pk, j + 3);
                    const float v2 = __uint_as_float((unsigned)(p2 >> 32));
                    const float v3 = __uint_as_float((unsigned)(p3 >> 32));
                    const uint2 q2 = __ldg(yb + (size_t)(unsigned)(p2 & 0xffffffffu) * 32 + lane);
                    const uint2 q3 = __ldg(yb + (size_t)(unsigned)(p3 & 0xffffffffu) * 32 + lane);
                    acc_pair(a0, v0, q0);
                    acc_pair(a1, v1, q1);
                    v0 = v2; v1 = v3; q0 = q2; q1 = q3;
                }
                // drain primed group
                acc_pair(a0, v0, q0);
                acc_pair(a1, v1, q1);
                j += 2;
            }
            if (j < m) {   // odd leftover edge
                const unsigned long long p0 = __shfl_sync(0xffffffffu, pk, j);
                const float v0 = __uint_as_float((unsigned)(p0 >> 32));
                const uint2 q0 = __ldg(yb + (size_t)(unsigned)(p0 & 0xffffffffu) * 32 + lane);
                acc_pair(a0, v0, q0);
            }
        }

        float4 r;
        r.x = fmaxf(a0.x + a1.x + bias4.x, 0.f);
        r.y = fmaxf(a0.y + a1.y + bias4.y, 0.f);
        r.z = fmaxf(a0.z + a1.z + bias4.z, 0.f);
        r.w = fmaxf(a0.w + a1.w + bias4.w, 0.f);

        __stcs(reinterpret_cast<float4*>(out) + ((size_t)b * N + n) * 32 + lane, r);
    }
}

// ---------------------------------------------------------------------------
// Launch: fork/join — CSR chain on stream 0, GEMM on side stream.
// ---------------------------------------------------------------------------
extern "C" void kernel_launch(void* const* d_in, const int* in_sizes, int n_in,
                              void* d_out, int out_size) {
    const float* x    = (const float*)d_in[0];
    const int*   er   = (const int*)  d_in[1];
    const int*   ec   = (const int*)  d_in[2];
    const float* ev   = (const float*)d_in[3];
    const float* W    = (const float*)d_in[4];
    const float* bias = (const float*)d_in[5];
    float*       out  = (float*)d_out;

    const int E  = in_sizes[1];
    const int C  = in_sizes[5];            // 128
    const int BN = in_sizes[0] / C;        // B*N
    const int N  = N_NODES;
    const int B  = BN / N;

    static cudaStream_t s_side = nullptr;
    static cudaEvent_t  ev_fork = nullptr, ev_join = nullptr;
    static bool         s_init = false;
    if (!s_init) {
        cudaStreamCreateWithFlags(&s_side, cudaStreamNonBlocking);
        cudaEventCreateWithFlags(&ev_fork, cudaEventDisableTiming);
        cudaEventCreateWithFlags(&ev_join, cudaEventDisableTiming);
        cudaFuncSetAttribute(gemm_kernel,
                             cudaFuncAttributeMaxDynamicSharedMemorySize,
                             2 * 128 * SPITCH * (int)sizeof(__half));
        s_init = true;
    }

    // Fork
    cudaEventRecord(ev_fork, (cudaStream_t)0);
    cudaStreamWaitEvent(s_side, ev_fork, 0);

    // Branch A (side stream): y = x @ W
    const int smem_bytes = 2 * 128 * SPITCH * (int)sizeof(__half);
    gemm_kernel<<<(BN + 127) / 128, 256, smem_bytes, s_side>>>(x, W, BN);
    cudaEventRecord(ev_join, s_side);

    // Branch B (origin stream): CSR build chain with multi-CTA scan
    zero_deg_kernel<<<(N + 255) / 256, 256>>>(N);
    hist_kernel<<<(E + 255) / 256, 256>>>(er, E);
    blocksum_kernel<<<SCAN_BLOCKS, 256>>>(N);
    scan_bsums_kernel<<<1, 32>>>(SCAN_BLOCKS, N);
    scanout_kernel<<<SCAN_BLOCKS, 256>>>(N);
    scatter_kernel<<<(E + 255) / 256, 256>>>(er, ec, ev, E);

    // Join
    cudaStreamWaitEvent((cudaStream_t)0, ev_join, 0);
    dim3 ggrid((N + 63) / 64, B);
    gather_kernel<<<ggrid, 256>>>(bias, out, N);
}

// round 16
// speedup vs baseline: 1.0886x; 1.0886x over previous
#include <cuda_runtime.h>
#include <cuda_fp16.h>
#include <cstdint>

// ---------------------------------------------------------------------------
// GCN layer: out = relu( (A x) @ W + b )  ==  relu( A (x@W) + b )
// R14 structure restored (gather reverted to known-best R8 loop).
// Change this round: CSR critical path trimmed (hist/scatter 2 edges/thread,
// int4 zero).
// ---------------------------------------------------------------------------

#define C_DIM 128
static constexpr int  N_NODES = 50000;
static constexpr int  B_MAX   = 4;
static constexpr int  E_MAX   = 800000;
static constexpr long Y_ELEMS = (long)B_MAX * N_NODES * C_DIM;

static constexpr int SCAN_CHUNK  = 1024;
static constexpr int SCAN_BLOCKS = (N_NODES + SCAN_CHUNK - 1) / SCAN_CHUNK; // 49

__device__ __align__(16) __half             g_yh[Y_ELEMS];     // 51.2 MB
__device__ __align__(16) int                g_deg[N_NODES + 4];
__device__ __align__(16) int                g_off[N_NODES + 4];
__device__ __align__(16) int                g_cur[N_NODES + 4];
__device__ int                              g_bsum[SCAN_BLOCKS];
__device__ int                              g_bbase[SCAN_BLOCKS];
__device__ __align__(16) unsigned long long g_ebuf[E_MAX];     // {val:hi, col:lo}

// ---------------------------------------------------------------------------
// CSR build
// ---------------------------------------------------------------------------
__global__ void zero_deg_kernel(int n4) {
    const int i = blockIdx.x * blockDim.x + threadIdx.x;
    if (i < n4) reinterpret_cast<int4*>(g_deg)[i] = make_int4(0, 0, 0, 0);
}

__global__ void hist_kernel(const int* __restrict__ er, int E) {
    const int i = (blockIdx.x * blockDim.x + threadIdx.x) * 2;
    if (i + 1 < E) {
        const int2 e2 = *reinterpret_cast<const int2*>(er + i);
        atomicAdd(&g_deg[e2.x], 1);
        atomicAdd(&g_deg[e2.y], 1);
    } else if (i < E) {
        atomicAdd(&g_deg[er[i]], 1);
    }
}

__global__ void __launch_bounds__(256) blocksum_kernel(int N) {
    __shared__ int wsum[8];
    const int tid  = threadIdx.x;
    const int lane = tid & 31;
    const int wid  = tid >> 5;
    const int i0   = blockIdx.x * SCAN_CHUNK + tid * 4;

    int4 d = make_int4(0, 0, 0, 0);
    if (i0 + 3 < N) {
        d = *reinterpret_cast<const int4*>(g_deg + i0);
    } else {
        if (i0 < N)     d.x = g_deg[i0];
        if (i0 + 1 < N) d.y = g_deg[i0 + 1];
        if (i0 + 2 < N) d.z = g_deg[i0 + 2];
    }
    int s = d.x + d.y + d.z + d.w;
#pragma unroll
    for (int o = 16; o > 0; o >>= 1) s += __shfl_down_sync(0xffffffffu, s, o);
    if (lane == 0) wsum[wid] = s;
    __syncthreads();
    if (tid == 0) {
        int t = 0;
#pragma unroll
        for (int w = 0; w < 8; ++w) t += wsum[w];
        g_bsum[blockIdx.x] = t;
    }
}

__global__ void scan_bsums_kernel(int nb, int N) {
    const int lane = threadIdx.x;
    int carry = 0;
    for (int base = 0; base < nb; base += 32) {
        const int i = base + lane;
        const int v0 = (i < nb) ? g_bsum[i] : 0;
        int v = v0;
#pragma unroll
        for (int o = 1; o < 32; o <<= 1) {
            const int t = __shfl_up_sync(0xffffffffu, v, o);
            if (lane >= o) v += t;
        }
        if (i < nb) g_bbase[i] = carry + v - v0;
        carry += __shfl_sync(0xffffffffu, v, 31);
    }
    if (lane == 0) g_off[N] = carry;
}

__global__ void __launch_bounds__(256) scanout_kernel(int N) {
    __shared__ int wbase[8];
    const int tid  = threadIdx.x;
    const int lane = tid & 31;
    const int wid  = tid >> 5;
    const int i0   = blockIdx.x * SCAN_CHUNK + tid * 4;

    int4 d = make_int4(0, 0, 0, 0);
    if (i0 + 3 < N) {
        d = *reinterpret_cast<const int4*>(g_deg + i0);
    } else {
        if (i0 < N)     d.x = g_deg[i0];
        if (i0 + 1 < N) d.y = g_deg[i0 + 1];
        if (i0 + 2 < N) d.z = g_deg[i0 + 2];
    }
    const int t = d.x + d.y + d.z + d.w;

    int v = t;
#pragma unroll
    for (int o = 1; o < 32; o <<= 1) {
        const int u = __shfl_up_sync(0xffffffffu, v, o);
        if (lane >= o) v += u;
    }
    if (lane == 31) wbase[wid] = v;
    __syncthreads();
    if (tid == 0) {
        int run = 0;
#pragma unroll
        for (int w = 0; w < 8; ++w) { const int tmp = wbase[w]; wbase[w] = run; run += tmp; }
    }
    __syncthreads();

    const int base = g_bbase[blockIdx.x] + wbase[wid] + (v - t);
    int4 off;
    off.x = base;
    off.y = off.x + d.x;
    off.z = off.y + d.y;
    off.w = off.z + d.z;

    if (i0 + 3 < N) {
        *reinterpret_cast<int4*>(g_off + i0) = off;
        *reinterpret_cast<int4*>(g_cur + i0) = off;
    } else {
        if (i0 < N)     { g_off[i0]     = off.x; g_cur[i0]     = off.x; }
        if (i0 + 1 < N) { g_off[i0 + 1] = off.y; g_cur[i0 + 1] = off.y; }
        if (i0 + 2 < N) { g_off[i0 + 2] = off.z; g_cur[i0 + 2] = off.z; }
    }
}

__global__ void scatter_kernel(const int*   __restrict__ er,
                               const int*   __restrict__ ec,
                               const float* __restrict__ ev,
                               int E) {
    const int i = (blockIdx.x * blockDim.x + threadIdx.x) * 2;
    if (i + 1 < E) {
        const int2   r2 = *reinterpret_cast<const int2*>(er + i);
        const int2   c2 = *reinterpret_cast<const int2*>(ec + i);
        const float2 v2 = *reinterpret_cast<const float2*>(ev + i);
        const int pos0 = atomicAdd(&g_cur[r2.x], 1);
        const int pos1 = atomicAdd(&g_cur[r2.y], 1);
        g_ebuf[pos0] = ((unsigned long long)__float_as_uint(v2.x) << 32) | (unsigned)c2.x;
        g_ebuf[pos1] = ((unsigned long long)__float_as_uint(v2.y) << 32) | (unsigned)c2.y;
    } else if (i < E) {
        const int pos = atomicAdd(&g_cur[er[i]], 1);
        g_ebuf[pos] = ((unsigned long long)__float_as_uint(ev[i]) << 32) | (unsigned)ec[i];
    }
}

// ---------------------------------------------------------------------------
// HMMA GEMM (unchanged)
// ---------------------------------------------------------------------------
static constexpr int SPITCH = 136;

__device__ __forceinline__ uint32_t smem_u32(const void* p) {
    return (uint32_t)__cvta_generic_to_shared(p);
}
__device__ __forceinline__ void ldsm_x4(uint32_t& r0, uint32_t& r1,
                                        uint32_t& r2, uint32_t& r3, uint32_t addr) {
    asm volatile("ldmatrix.sync.aligned.m8n8.x4.shared.b16 {%0,%1,%2,%3}, [%4];"
                 : "=r"(r0), "=r"(r1), "=r"(r2), "=r"(r3) : "r"(addr));
}
__device__ __forceinline__ void ldsm_x4_t(uint32_t& r0, uint32_t& r1,
                                          uint32_t& r2, uint32_t& r3, uint32_t addr) {
    asm volatile("ldmatrix.sync.aligned.m8n8.x4.trans.shared.b16 {%0,%1,%2,%3}, [%4];"
                 : "=r"(r0), "=r"(r1), "=r"(r2), "=r"(r3) : "r"(addr));
}
__device__ __forceinline__ void mma_16816(float& d0, float& d1, float& d2, float& d3,
                                          uint32_t a0, uint32_t a1, uint32_t a2, uint32_t a3,
                                          uint32_t b0, uint32_t b1) {
    asm volatile(
        "mma.sync.aligned.m16n8k16.row.col.f32.f16.f16.f32 "
        "{%0,%1,%2,%3}, {%4,%5,%6,%7}, {%8,%9}, {%0,%1,%2,%3};"
        : "+f"(d0), "+f"(d1), "+f"(d2), "+f"(d3)
        : "r"(a0), "r"(a1), "r"(a2), "r"(a3), "r"(b0), "r"(b1));
}

__global__ void __launch_bounds__(256)
gemm_kernel(const float* __restrict__ x,
            const float* __restrict__ W,
            int total_rows) {
    extern __shared__ __half sh[];
    __half* As = sh;
    __half* Ws = sh + 128 * SPITCH;

    const int tid    = threadIdx.x;
    const int lane   = tid & 31;
    const int warp   = tid >> 5;
    const int warp_m = warp >> 1;
    const int warp_n = warp & 1;
    const long row0  = (long)blockIdx.x * 128;

    {
        const float4* Wg = reinterpret_cast<const float4*>(W);
        const float4* Ag = reinterpret_cast<const float4*>(x);
#pragma unroll
        for (int j = 0; j < 16; ++j) {
            const int i  = tid + j * 256;
            const int r  = i >> 5;
            const int c4 = i & 31;
            {
                const float4 v = __ldg(Wg + i);
                __half2 h0 = __floats2half2_rn(v.x, v.y);
                __half2 h1 = __floats2half2_rn(v.z, v.w);
                uint2 pk;
                pk.x = *reinterpret_cast<const unsigned*>(&h0);
                pk.y = *reinterpret_cast<const unsigned*>(&h1);
                *reinterpret_cast<uint2*>(Ws + r * SPITCH + c4 * 4) = pk;
            }
            {
                const long gr = row0 + r;
                float4 v = make_float4(0.f, 0.f, 0.f, 0.f);
                if (gr < total_rows) v = __ldcs(Ag + gr * 32 + c4);
                __half2 h0 = __floats2half2_rn(v.x, v.y);
                __half2 h1 = __floats2half2_rn(v.z, v.w);
                uint2 pk;
                pk.x = *reinterpret_cast<const unsigned*>(&h0);
                pk.y = *reinterpret_cast<const unsigned*>(&h1);
                *reinterpret_cast<uint2*>(As + r * SPITCH + c4 * 4) = pk;
            }
        }
    }
    __syncthreads();

    const int lrow = lane & 15;
    const int lcol = (lane >> 4) * 8;
    const uint32_t a_base = smem_u32(As) +
        (uint32_t)(((warp_m * 32 + lrow) * SPITCH + lcol) * 2);
    const uint32_t b_base = smem_u32(Ws) +
        (uint32_t)((lrow * SPITCH + warp_n * 64 + lcol) * 2);

    float acc[2][8][4];
#pragma unroll
    for (int mt = 0; mt < 2; ++mt)
#pragma unroll
        for (int nt = 0; nt < 8; ++nt)
#pragma unroll
            for (int q = 0; q < 4; ++q) acc[mt][nt][q] = 0.f;

#pragma unroll
    for (int kk = 0; kk < 8; ++kk) {
        uint32_t a[2][4];
        ldsm_x4(a[0][0], a[0][1], a[0][2], a[0][3],
                a_base + (uint32_t)(kk * 16 * 2));
        ldsm_x4(a[1][0], a[1][1], a[1][2], a[1][3],
                a_base + (uint32_t)((16 * SPITCH + kk * 16) * 2));

        uint32_t b[4][4];
#pragma unroll
        for (int nt16 = 0; nt16 < 4; ++nt16) {
            ldsm_x4_t(b[nt16][0], b[nt16][1], b[nt16][2], b[nt16][3],
                      b_base + (uint32_t)((kk * 16 * SPITCH + nt16 * 16) * 2));
        }

#pragma unroll
        for (int mt = 0; mt < 2; ++mt)
#pragma unroll
            for (int nt16 = 0; nt16 < 4; ++nt16) {
                mma_16816(acc[mt][nt16 * 2][0], acc[mt][nt16 * 2][1],
                          acc[mt][nt16 * 2][2], acc[mt][nt16 * 2][3],
                          a[mt][0], a[mt][1], a[mt][2], a[mt][3],
                          b[nt16][0], b[nt16][1]);
                mma_16816(acc[mt][nt16 * 2 + 1][0], acc[mt][nt16 * 2 + 1][1],
                          acc[mt][nt16 * 2 + 1][2], acc[mt][nt16 * 2 + 1][3],
                          a[mt][0], a[mt][1], a[mt][2], a[mt][3],
                          b[nt16][2], b[nt16][3]);
            }
    }

    __syncthreads();
    {
        const int g = lane >> 2;
        const int c = (lane & 3) * 2;
#pragma unroll
        for (int mt = 0; mt < 2; ++mt) {
#pragma unroll
            for (int nt = 0; nt < 8; ++nt) {
                const int row = warp_m * 32 + mt * 16 + g;
                const int col = warp_n * 64 + nt * 8 + c;
                __half2 lo = __floats2half2_rn(acc[mt][nt][0], acc[mt][nt][1]);
                __half2 hi = __floats2half2_rn(acc[mt][nt][2], acc[mt][nt][3]);
                *reinterpret_cast<__half2*>(As + row * SPITCH + col)       = lo;
                *reinterpret_cast<__half2*>(As + (row + 8) * SPITCH + col) = hi;
            }
        }
    }
    __syncthreads();
    {
#pragma unroll
        for (int j = 0; j < 8; ++j) {
            const int chunk = tid + j * 256;
            const int r   = chunk >> 4;
            const int c16 = chunk & 15;
            const long gr = row0 + r;
            if (gr < total_rows) {
                const uint4 v = *reinterpret_cast<const uint4*>(As + r * SPITCH + c16 * 8);
                *reinterpret_cast<uint4*>(g_yh + gr * C_DIM + c16 * 8) = v;
            }
        }
    }
}

// ---------------------------------------------------------------------------
// Gather (R8/R14 known-best loop, restored verbatim)
// ---------------------------------------------------------------------------
__global__ void __launch_bounds__(256)
gather_kernel(const float* __restrict__ bias,
              float*       __restrict__ out,
              int N) {
    const int lane = threadIdx.x & 31;
    const int warp = threadIdx.x >> 5;
    const int b    = blockIdx.y;

    const uint2* yb    = reinterpret_cast<const uint2*>(g_yh) + (size_t)b * N * 32;
    const float4 bias4 = __ldg(reinterpret_cast<const float4*>(bias) + lane);

    const int n_base = blockIdx.x * 64;

#pragma unroll 1
    for (int i = 0; i < 8; ++i) {
        const int n = n_base + warp * 8 + i;
        if (n >= N) return;

        const int st = __ldg(&g_off[n]);
        const int en = __ldg(&g_off[n + 1]);

        float4 a0 = make_float4(0.f, 0.f, 0.f, 0.f);
        float4 a1 = make_float4(0.f, 0.f, 0.f, 0.f);

        for (int base = st; base < en; base += 32) {
            const int m = min(32, en - base);
            unsigned long long pk = 0;
            if (lane < m) pk = __ldcs(&g_ebuf[base + lane]);

            int j = 0;
            for (; j + 1 < m; j += 2) {
                const unsigned long long p0 = __shfl_sync(0xffffffffu, pk, j);
                const unsigned long long p1 = __shfl_sync(0xffffffffu, pk, j + 1);
                const int   c0 = (int)(p0 & 0xffffffffu);
                const int   c1 = (int)(p1 & 0xffffffffu);
                const float v0 = __uint_as_float((unsigned)(p0 >> 32));
                const float v1 = __uint_as_float((unsigned)(p1 >> 32));
                const uint2 q0 = __ldg(yb + (size_t)c0 * 32 + lane);
                const uint2 q1 = __ldg(yb + (size_t)c1 * 32 + lane);

                const float2 f0a = __half22float2(*reinterpret_cast<const __half2*>(&q0.x));
                const float2 f0b = __half22float2(*reinterpret_cast<const __half2*>(&q0.y));
                const float2 f1a = __half22float2(*reinterpret_cast<const __half2*>(&q1.x));
                const float2 f1b = __half22float2(*reinterpret_cast<const __half2*>(&q1.y));

                a0.x = fmaf(v0, f0a.x, a0.x); a0.y = fmaf(v0, f0a.y, a0.y);
                a0.z = fmaf(v0, f0b.x, a0.z); a0.w = fmaf(v0, f0b.y, a0.w);
                a1.x = fmaf(v1, f1a.x, a1.x); a1.y = fmaf(v1, f1a.y, a1.y);
                a1.z = fmaf(v1, f1b.x, a1.z); a1.w = fmaf(v1, f1b.y, a1.w);
            }
            if (j < m) {
                const unsigned long long p0 = __shfl_sync(0xffffffffu, pk, j);
                const int   c0 = (int)(p0 & 0xffffffffu);
                const float v0 = __uint_as_float((unsigned)(p0 >> 32));
                const uint2 q0 = __ldg(yb + (size_t)c0 * 32 + lane);
                const float2 f0a = __half22float2(*reinterpret_cast<const __half2*>(&q0.x));
                const float2 f0b = __half22float2(*reinterpret_cast<const __half2*>(&q0.y));
                a0.x = fmaf(v0, f0a.x, a0.x); a0.y = fmaf(v0, f0a.y, a0.y);
                a0.z = fmaf(v0, f0b.x, a0.z); a0.w = fmaf(v0, f0b.y, a0.w);
            }
        }

        float4 r;
        r.x = fmaxf(a0.x + a1.x + bias4.x, 0.f);
        r.y = fmaxf(a0.y + a1.y + bias4.y, 0.f);
        r.z = fmaxf(a0.z + a1.z + bias4.z, 0.f);
        r.w = fmaxf(a0.w + a1.w + bias4.w, 0.f);

        __stcs(reinterpret_cast<float4*>(out) + ((size_t)b * N + n) * 32 + lane, r);
    }
}

// ---------------------------------------------------------------------------
// Launch: fork/join — CSR chain on stream 0, GEMM on side stream.
// ---------------------------------------------------------------------------
extern "C" void kernel_launch(void* const* d_in, const int* in_sizes, int n_in,
                              void* d_out, int out_size) {
    const float* x    = (const float*)d_in[0];
    const int*   er   = (const int*)  d_in[1];
    const int*   ec   = (const int*)  d_in[2];
    const float* ev   = (const float*)d_in[3];
    const float* W    = (const float*)d_in[4];
    const float* bias = (const float*)d_in[5];
    float*       out  = (float*)d_out;

    const int E  = in_sizes[1];
    const int C  = in_sizes[5];            // 128
    const int BN = in_sizes[0] / C;        // B*N
    const int N  = N_NODES;
    const int B  = BN / N;

    static cudaStream_t s_side = nullptr;
    static cudaEvent_t  ev_fork = nullptr, ev_join = nullptr;
    static bool         s_init = false;
    if (!s_init) {
        cudaStreamCreateWithFlags(&s_side, cudaStreamNonBlocking);
        cudaEventCreateWithFlags(&ev_fork, cudaEventDisableTiming);
        cudaEventCreateWithFlags(&ev_join, cudaEventDisableTiming);
        cudaFuncSetAttribute(gemm_kernel,
                             cudaFuncAttributeMaxDynamicSharedMemorySize,
                             2 * 128 * SPITCH * (int)sizeof(__half));
        s_init = true;
    }

    // Fork
    cudaEventRecord(ev_fork, (cudaStream_t)0);
    cudaStreamWaitEvent(s_side, ev_fork, 0);

    // Branch A (side stream): y = x @ W
    const int smem_bytes = 2 * 128 * SPITCH * (int)sizeof(__half);
    gemm_kernel<<<(BN + 127) / 128, 256, smem_bytes, s_side>>>(x, W, BN);
    cudaEventRecord(ev_join, s_side);

    // Branch B (origin stream): CSR build chain with multi-CTA scan
    zero_deg_kernel<<<((N + 3) / 4 + 255) / 256, 256>>>((N + 3) / 4);
    hist_kernel<<<((E + 1) / 2 + 255) / 256, 256>>>(er, E);
    blocksum_kernel<<<SCAN_BLOCKS, 256>>>(N);
    scan_bsums_kernel<<<1, 32>>>(SCAN_BLOCKS, N);
    scanout_kernel<<<SCAN_BLOCKS, 256>>>(N);
    scatter_kernel<<<((E + 1) / 2 + 255) / 256, 256>>>(er, ec, ev, E);

    // Join
    cudaStreamWaitEvent((cudaStream_t)0, ev_join, 0);
    dim3 ggrid((N + 63) / 64, B);
    gather_kernel<<<ggrid, 256>>>(bias, out, N);
}